// round 8
// baseline (speedup 1.0000x reference)
#include <cuda_runtime.h>
#include <math.h>

#define EPS      1e-5f
#define LSEQ     32
#define DM       128
#define CIN      96
#define COUT     12
#define DIN      256
#define DST      16
#define NH       8
#define CDIM     288          // DIN + 2*DST
#define EPROJ    552          // 2*DIN + 2*DST + NH
#define TST      34           // hs transposed stride
#define NT       512
#define MAXB     1024

typedef unsigned long long u64;

// device scratch (no allocation) — non-duplicated transposed weights
#define IPT_N (4 * DM * EPROJ)     // [blk][k][e] = ipw[e][k]*bnw[k]
#define OPT_N (4 * DIN * DM)       // [blk][e][d] = opw[d][e]*mnw[e]
__device__ float g_ipt[IPT_N];
__device__ float g_opt[OPT_N];
__device__ float g_A[(size_t)MAXB * 2 * DM];

// shared memory layout (floats)
#define OFF_BUF   0                          // 3072
#define OFF_HST   (OFF_BUF + CIN*LSEQ)       // 128*34 = 4352
#define OFF_ZX    (OFF_HST + DM*TST)         // 32*552 = 17664
#define OFF_DT    (OFF_ZX + LSEQ*EPROJ)      // 256
#define OFF_DA    (OFF_DT + LSEQ*NH)         // 256
#define OFF_INV   (OFF_DA + LSEQ*NH)         // 32
#define OFF_INV2  (OFF_INV + LSEQ)           // 32
#define OFF_RED   (OFF_INV2 + LSEQ)          // 512
#define SMEM_FLOATS (OFF_RED + NT)           // 26176 floats = 104704 B

__device__ __forceinline__ float sigmoidf_(float v) {
    return 1.f / (1.f + __expf(-v));
}
__device__ __forceinline__ u64 pk2(float lo, float hi) {
    u64 r; asm("mov.b64 %0,{%1,%2};" : "=l"(r) : "f"(lo), "f"(hi)); return r;
}
__device__ __forceinline__ u64 dup2(float v) { return pk2(v, v); }
__device__ __forceinline__ void upk2(u64 a, float& lo, float& hi) {
    asm("mov.b64 {%0,%1},%2;" : "=f"(lo), "=f"(hi) : "l"(a));
}
__device__ __forceinline__ u64 fma2_(u64 a, u64 b, u64 c) {
    u64 d; asm("fma.rn.f32x2 %0,%1,%2,%3;" : "=l"(d) : "l"(a), "l"(b), "l"(c)); return d;
}
__device__ __forceinline__ u64 mul2_(u64 a, u64 b) {
    u64 d; asm("mul.rn.f32x2 %0,%1,%2;" : "=l"(d) : "l"(a), "l"(b)); return d;
}

// ---- pre-kernel: transpose + fold norms into weights ------------------------
__global__ void prep_weights(const float* __restrict__ ipw,
                             const float* __restrict__ bnw,
                             const float* __restrict__ opw,
                             const float* __restrict__ mnw) {
    int i = blockIdx.x * blockDim.x + threadIdx.x;
    if (i < IPT_N) {
        int blk = i / (DM * EPROJ);
        int r   = i - blk * (DM * EPROJ);
        int k   = r / EPROJ;
        int e   = r - k * EPROJ;
        g_ipt[i] = ipw[((size_t)blk * EPROJ + e) * DM + k] * bnw[blk * DM + k];
    } else if (i < IPT_N + OPT_N) {
        int j   = i - IPT_N;
        int blk = j / (DIN * DM);
        int r   = j - blk * (DIN * DM);
        int e   = r / DM;
        int d   = r - e * DM;
        g_opt[j] = opw[((size_t)blk * DM + d) * DIN + e] * mnw[blk * DIN + e];
    }
}

// ---- finalize ----------------------------------------------------------------
__global__ void finalize_kernel(const float* __restrict__ fow,
                                const float* __restrict__ fob,
                                const float* __restrict__ olw,
                                const float* __restrict__ olb,
                                float* __restrict__ out, int B) {
    int idx = blockIdx.x * blockDim.x + threadIdx.x;
    if (idx >= B * COUT) return;
    int b = idx / COUT, o = idx - b * COUT;
    float Swl = 0.f;
#pragma unroll
    for (int t = 0; t < LSEQ; t++) Swl += olw[t];
    const float* A0 = g_A + (size_t)b * 2 * DM;
    float acc = 0.f;
#pragma unroll 4
    for (int d = 0; d < DM; d++) acc = fmaf(fow[o * DM + d], A0[d] + A0[DM + d], acc);
    out[idx] = acc + fob[o] * Swl + olb[0];
}

// ---- main: one CTA per (batch, direction), 512 threads ------------------------
__global__ void __launch_bounds__(NT, 2) mamba_actor_kernel(
    const float* __restrict__ x,        // (B, 96)
    const float* __restrict__ buffer,   // (B, 96, 32)
    const float* __restrict__ fiw,      // (128, 96)
    const float* __restrict__ fib,      // (128,)
    const float* __restrict__ cw,       // (4, 288, 4)
    const float* __restrict__ cb,       // (4, 288)
    const float* __restrict__ dtb,      // (4, 8)
    const float* __restrict__ alog,     // (4, 8)
    const float* __restrict__ Dp,       // (4, 8)
    const float* __restrict__ nfw,      // (2, 128)
    const float* __restrict__ olw,      // (1, 32)
    float* __restrict__ out)
{
    extern __shared__ float sm[];
    float* s_buf  = sm + OFF_BUF;
    float* s_hsT  = sm + OFF_HST;   // [d][t], stride TST
    float* s_zx   = sm + OFF_ZX;    // [t][e], stride EPROJ
    float* s_dt   = sm + OFF_DT;
    float* s_dA   = sm + OFF_DA;
    float* s_inv  = sm + OFF_INV;
    float* s_inv2 = sm + OFF_INV2;
    float* s_red  = sm + OFF_RED;

    const int B    = gridDim.x >> 1;
    const int b    = blockIdx.x >> 1;
    const int dir  = blockIdx.x & 1;
    const int tid  = threadIdx.x;
    const int lane = tid & 31;
    const int warp = tid >> 5;

    // ---- Stage 0: shifted buffer -> smem (dir-flipped) + buf output ----------
    {
        const float* bsrc = buffer + (size_t)b * CIN * LSEQ;
        const float* xsrc = x + (size_t)b * CIN;
        float* bdst = out + (size_t)B * COUT + (size_t)b * CIN * LSEQ;
        for (int idx = tid; idx < CIN * LSEQ; idx += NT) {
            int c = idx >> 5, l = idx & 31;
            float v = (l < LSEQ - 1) ? bsrc[c * LSEQ + l + 1] : xsrc[c];
            int ls = dir ? (LSEQ - 1 - l) : l;
            s_buf[c * LSEQ + ls] = v;
            if (dir == 0) bdst[idx] = v;
        }
    }
    __syncthreads();

    // ---- fc_in (f32x2): thread = (d, t-quarter), 4 pairs each ----------------
    {
        int d  = tid >> 2;
        int t0 = (tid & 3) * 8;
        u64 acc2[4];
        u64 bias = dup2(fib[d]);
#pragma unroll
        for (int p = 0; p < 4; p++) acc2[p] = bias;
        const float4* wrow = reinterpret_cast<const float4*>(fiw + d * CIN);
#pragma unroll 2
        for (int cc = 0; cc < CIN / 4; cc++) {
            float4 w4 = wrow[cc];
            u64 w0 = dup2(w4.x), w1 = dup2(w4.y), w2 = dup2(w4.z), w3 = dup2(w4.w);
            const u64* b0 = reinterpret_cast<const u64*>(s_buf + (cc * 4 + 0) * LSEQ + t0);
            const u64* b1 = reinterpret_cast<const u64*>(s_buf + (cc * 4 + 1) * LSEQ + t0);
            const u64* b2 = reinterpret_cast<const u64*>(s_buf + (cc * 4 + 2) * LSEQ + t0);
            const u64* b3 = reinterpret_cast<const u64*>(s_buf + (cc * 4 + 3) * LSEQ + t0);
#pragma unroll
            for (int p = 0; p < 4; p++) {
                acc2[p] = fma2_(b0[p], w0, acc2[p]);
                acc2[p] = fma2_(b1[p], w1, acc2[p]);
                acc2[p] = fma2_(b2[p], w2, acc2[p]);
                acc2[p] = fma2_(b3[p], w3, acc2[p]);
            }
        }
        u64* hdst = reinterpret_cast<u64*>(s_hsT + d * TST + t0);
#pragma unroll
        for (int p = 0; p < 4; p++) hdst[p] = acc2[p];
    }
    __syncthreads();

    for (int l = 0; l < 2; l++) {
        const int blk = dir * 2 + l;

        // ---- block rmsnorm over d: warp covers 8 d-rows -----------------------
        {
            float s = 0.f;
#pragma unroll
            for (int q = 0; q < 8; q++) {
                float v = s_hsT[(warp * 8 + q) * TST + lane];
                s += v * v;
            }
            s_red[warp * 32 + lane] = s;
        }
        __syncthreads();
        if (tid < 32) {
            float s = 0.f;
#pragma unroll
            for (int w = 0; w < 16; w++) s += s_red[w * 32 + tid];
            s_inv[tid] = rsqrtf(s * (1.f / DM) + EPS);
        }
        __syncthreads();

        // ---- in_proj (f32x2): 4e x 8t tiles, 512 exact units ------------------
        {
            const float* Wt = g_ipt + (size_t)blk * DM * EPROJ;
            // main: cols 0..511
            {
                int g  = tid & 127;
                int t0 = (tid >> 7) * 8;     // 0,8,16,24
                int e0 = g * 4;
                u64 acc[4][4];
#pragma unroll
                for (int j = 0; j < 4; j++)
#pragma unroll
                    for (int p = 0; p < 4; p++) acc[j][p] = 0ull;
#pragma unroll 1
                for (int kc = 0; kc < DM / 4; kc++) {
#pragma unroll
                    for (int k = 0; k < 4; k++) {
                        float4 w = *reinterpret_cast<const float4*>(
                            Wt + (kc * 4 + k) * EPROJ + e0);
                        u64 wx = dup2(w.x), wy = dup2(w.y);
                        u64 wz = dup2(w.z), ww = dup2(w.w);
                        const u64* hp_ = reinterpret_cast<const u64*>(
                            s_hsT + (kc * 4 + k) * TST + t0);
#pragma unroll
                        for (int p = 0; p < 4; p++) {
                            u64 h = hp_[p];
                            acc[0][p] = fma2_(h, wx, acc[0][p]);
                            acc[1][p] = fma2_(h, wy, acc[1][p]);
                            acc[2][p] = fma2_(h, wz, acc[2][p]);
                            acc[3][p] = fma2_(h, ww, acc[3][p]);
                        }
                    }
                }
#pragma unroll
                for (int p = 0; p < 4; p++) {
                    u64 inv2p = *reinterpret_cast<const u64*>(s_inv + t0 + 2 * p);
                    float4 o0, o1;
                    u64 a;
                    a = mul2_(acc[0][p], inv2p); upk2(a, o0.x, o1.x);
                    a = mul2_(acc[1][p], inv2p); upk2(a, o0.y, o1.y);
                    a = mul2_(acc[2][p], inv2p); upk2(a, o0.z, o1.z);
                    a = mul2_(acc[3][p], inv2p); upk2(a, o0.w, o1.w);
                    *reinterpret_cast<float4*>(s_zx + (t0 + 2 * p + 0) * EPROJ + e0) = o0;
                    *reinterpret_cast<float4*>(s_zx + (t0 + 2 * p + 1) * EPROJ + e0) = o1;
                }
            }
            // tail: cols 512..551 (1e x 8t per unit, 160 units)
            if (tid < 160) {
                int e  = 512 + (tid >> 2);
                int t0 = (tid & 3) * 8;
                u64 acc[4];
#pragma unroll
                for (int p = 0; p < 4; p++) acc[p] = 0ull;
#pragma unroll 2
                for (int kc = 0; kc < DM / 4; kc++) {
#pragma unroll
                    for (int k = 0; k < 4; k++) {
                        u64 wd = dup2(Wt[(kc * 4 + k) * EPROJ + e]);
                        const u64* hp_ = reinterpret_cast<const u64*>(
                            s_hsT + (kc * 4 + k) * TST + t0);
#pragma unroll
                        for (int p = 0; p < 4; p++) acc[p] = fma2_(hp_[p], wd, acc[p]);
                    }
                }
#pragma unroll
                for (int p = 0; p < 4; p++) {
                    float lo, hi;
                    u64 inv2p = *reinterpret_cast<const u64*>(s_inv + t0 + 2 * p);
                    upk2(mul2_(acc[p], inv2p), lo, hi);
                    s_zx[(t0 + 2 * p + 0) * EPROJ + e] = lo;
                    s_zx[(t0 + 2 * p + 1) * EPROJ + e] = hi;
                }
            }
        }
        __syncthreads();

        // ---- dt/dA (threads 0..255) + conv boundary pre-reads -----------------
        if (tid < 256) {
            int t = tid >> 3, h = tid & 7;
            float v  = s_zx[t * EPROJ + DIN + CDIM + h] + dtb[blk * NH + h];
            float sp = (v > 20.f) ? v : log1pf(__expf(v));
            s_dt[t * NH + h] = sp;
            s_dA[t * NH + h] = __expf(-__expf(alog[blk * NH + h]) * sp);
        }
        float pre[2][3];
        {
            int nb = 0;
            for (int u = tid; u < 2 * CDIM; u += NT) {
                if (u >= CDIM) {
                    float* col = s_zx + DIN + (u - CDIM);
                    pre[nb][0] = col[13 * EPROJ];
                    pre[nb][1] = col[14 * EPROJ];
                    pre[nb][2] = col[15 * EPROJ];
                    nb++;
                }
            }
        }
        __syncthreads();

        // ---- causal depthwise conv (k=4) + silu, (c, t-half) units ------------
        {
            int nb = 0;
            for (int u = tid; u < 2 * CDIM; u += NT) {
                int half = (u >= CDIM);
                int c = half ? u - CDIM : u;
                float4 w4 = *reinterpret_cast<const float4*>(cw + ((size_t)blk * CDIM + c) * 4);
                float bb  = cb[blk * CDIM + c];
                float x0, x1, x2;
                if (half) { x0 = pre[nb][0]; x1 = pre[nb][1]; x2 = pre[nb][2]; nb++; }
                else      { x0 = 0.f; x1 = 0.f; x2 = 0.f; }
                float* col = s_zx + DIN + c + (half ? 16 * EPROJ : 0);
#pragma unroll
                for (int tt = 0; tt < 16; tt++) {
                    float xc = col[tt * EPROJ];
                    float o  = fmaf(w4.x, x0, fmaf(w4.y, x1, fmaf(w4.z, x2, fmaf(w4.w, xc, bb))));
                    col[tt * EPROJ] = o * sigmoidf_(o);
                    x0 = x1; x1 = x2; x2 = xc;
                }
            }
        }
        __syncthreads();

        // ---- SSM scan (+ fused gate): thread pair = (hp, n-half) --------------
        {
            int hp = tid >> 1;         // 0..255: (head, p)
            int h  = hp >> 5;
            int nh = tid & 1;          // owns states nh*8 .. nh*8+8
            u64 st2[4];
#pragma unroll
            for (int n = 0; n < 4; n++) st2[n] = 0ull;
            float dskip = Dp[blk * NH + h];
            for (int t = 0; t < LSEQ; t++) {
                float* row = s_zx + t * EPROJ;
                float dAv = s_dA[t * NH + h];
                float dtv = s_dt[t * NH + h];
                float xv  = row[DIN + hp];
                u64 dA2  = dup2(dAv);
                u64 dtx2 = dup2(dtv * xv);
                const ulonglong2* Bp = reinterpret_cast<const ulonglong2*>(row + 2 * DIN + nh * 8);
                const ulonglong2* Cp = reinterpret_cast<const ulonglong2*>(row + 2 * DIN + DST + nh * 8);
                u64 y2 = 0ull;
#pragma unroll
                for (int q = 0; q < 2; q++) {
                    ulonglong2 b2 = Bp[q];
                    ulonglong2 c2 = Cp[q];
                    st2[2*q]   = fma2_(st2[2*q],   dA2, mul2_(dtx2, b2.x));
                    y2         = fma2_(st2[2*q],   c2.x, y2);
                    st2[2*q+1] = fma2_(st2[2*q+1], dA2, mul2_(dtx2, b2.y));
                    y2         = fma2_(st2[2*q+1], c2.y, y2);
                }
                float ylo, yhi;
                upk2(y2, ylo, yhi);
                float y = ylo + yhi;
                y += __shfl_xor_sync(0xffffffffu, y, 1);
                if (nh == 0) {
                    float z = row[hp];
                    row[DIN + hp] = fmaf(dskip, xv, y) * z * sigmoidf_(z);
                }
            }
        }
        __syncthreads();

        // ---- mixer rmsnorm over gated g: 16 parts of 16 floats per t ----------
        {
            int t = tid >> 4, part = tid & 15;
            const float4* gp = reinterpret_cast<const float4*>(s_zx + t * EPROJ + DIN + part * 16);
            float s = 0.f;
#pragma unroll
            for (int q = 0; q < 4; q++) {
                float4 v = gp[q];
                s += v.x * v.x + v.y * v.y + v.z * v.z + v.w * v.w;
            }
            s += __shfl_xor_sync(0xffffffffu, s, 1);
            s += __shfl_xor_sync(0xffffffffu, s, 2);
            s += __shfl_xor_sync(0xffffffffu, s, 4);
            s += __shfl_xor_sync(0xffffffffu, s, 8);
            if (part == 0) s_inv2[t] = rsqrtf(s * (1.f / DIN) + EPS);
        }
        __syncthreads();

        // ---- out_proj + residual (f32x2): 2d x 4t tiles, 512 exact units ------
        {
            int ttile = tid >> 6;      // 0..7 -> t0 = ttile*4
            int dg    = tid & 63;      // d0 = dg*2
            int t0 = ttile * 4, d0 = dg * 2;
            const float* Ot = g_opt + (size_t)blk * DIN * DM;
            u64 acc[2][2];
#pragma unroll
            for (int j = 0; j < 2; j++)
#pragma unroll
                for (int p = 0; p < 2; p++) acc[j][p] = 0ull;
#pragma unroll 1
            for (int ec = 0; ec < DIN / 4; ec++) {
                float2 w0 = *reinterpret_cast<const float2*>(Ot + (ec * 4 + 0) * DM + d0);
                float2 w1 = *reinterpret_cast<const float2*>(Ot + (ec * 4 + 1) * DM + d0);
                float2 w2 = *reinterpret_cast<const float2*>(Ot + (ec * 4 + 2) * DM + d0);
                float2 w3 = *reinterpret_cast<const float2*>(Ot + (ec * 4 + 3) * DM + d0);
                u64 w0x = dup2(w0.x), w1x = dup2(w1.x), w2x = dup2(w2.x), w3x = dup2(w3.x);
                u64 w0y = dup2(w0.y), w1y = dup2(w1.y), w2y = dup2(w2.y), w3y = dup2(w3.y);
#pragma unroll
                for (int p = 0; p < 2; p++) {
                    float4 ga = *reinterpret_cast<const float4*>(
                        s_zx + (t0 + 2 * p + 0) * EPROJ + DIN + ec * 4);
                    float4 gb = *reinterpret_cast<const float4*>(
                        s_zx + (t0 + 2 * p + 1) * EPROJ + DIN + ec * 4);
                    u64 gx = pk2(ga.x, gb.x), gy = pk2(ga.y, gb.y);
                    u64 gz = pk2(ga.z, gb.z), gw = pk2(ga.w, gb.w);
                    acc[0][p] = fma2_(gx, w0x, acc[0][p]);
                    acc[0][p] = fma2_(gy, w1x, acc[0][p]);
                    acc[0][p] = fma2_(gz, w2x, acc[0][p]);
                    acc[0][p] = fma2_(gw, w3x, acc[0][p]);
                    acc[1][p] = fma2_(gx, w0y, acc[1][p]);
                    acc[1][p] = fma2_(gy, w1y, acc[1][p]);
                    acc[1][p] = fma2_(gz, w2y, acc[1][p]);
                    acc[1][p] = fma2_(gw, w3y, acc[1][p]);
                }
            }
#pragma unroll
            for (int j = 0; j < 2; j++)
#pragma unroll
                for (int p = 0; p < 2; p++) {
                    u64 inv2p = *reinterpret_cast<const u64*>(s_inv2 + t0 + 2 * p);
                    u64* hpw = reinterpret_cast<u64*>(s_hsT + (d0 + j) * TST + t0 + 2 * p);
                    *hpw = fma2_(acc[j][p], inv2p, *hpw);
                }
        }
        __syncthreads();
    } // layer

    // ---- final rmsnorm(norm_f) over d ------------------------------------------
    {
        float s = 0.f;
#pragma unroll
        for (int q = 0; q < 8; q++) {
            float v = s_hsT[(warp * 8 + q) * TST + lane];
            s += v * v;
        }
        s_red[warp * 32 + lane] = s;
    }
    __syncthreads();
    if (tid < 32) {
        float s = 0.f;
#pragma unroll
        for (int w = 0; w < 16; w++) s += s_red[w * 32 + tid];
        s_inv[tid] = rsqrtf(s * (1.f / DM) + EPS);
    }
    __syncthreads();

    // ---- L-weighted accumulate -> g_A ------------------------------------------
    if (tid < DM) {
        const float* hrow = s_hsT + tid * TST;
        float s = 0.f;
#pragma unroll
        for (int t = 0; t < LSEQ; t++) {
            float wl = olw[dir ? (LSEQ - 1 - t) : t];
            s = fmaf(wl * s_inv[t], hrow[t], s);
        }
        g_A[((size_t)b * 2 + dir) * DM + tid] = s * nfw[dir * DM + tid];
    }
}

extern "C" void kernel_launch(void* const* d_in, const int* in_sizes, int n_in,
                              void* d_out, int out_size) {
    const float* x      = (const float*)d_in[0];
    const float* buffer = (const float*)d_in[1];
    const float* fiw    = (const float*)d_in[2];
    const float* fib    = (const float*)d_in[3];
    const float* bnw    = (const float*)d_in[4];
    const float* ipw    = (const float*)d_in[5];
    const float* cw     = (const float*)d_in[6];
    const float* cb     = (const float*)d_in[7];
    const float* dtb    = (const float*)d_in[8];
    const float* alog   = (const float*)d_in[9];
    const float* Dp     = (const float*)d_in[10];
    const float* mnw    = (const float*)d_in[11];
    const float* opw    = (const float*)d_in[12];
    const float* nfw    = (const float*)d_in[13];
    const float* fow    = (const float*)d_in[14];
    const float* fob    = (const float*)d_in[15];
    const float* olw    = (const float*)d_in[16];
    const float* olb    = (const float*)d_in[17];
    float* out = (float*)d_out;

    int B = in_sizes[0] / CIN;   // 1024
    size_t smem_bytes = (size_t)SMEM_FLOATS * sizeof(float);

    cudaFuncSetAttribute(mamba_actor_kernel,
                         cudaFuncAttributeMaxDynamicSharedMemorySize,
                         (int)smem_bytes);

    int prep_total = IPT_N + OPT_N;
    prep_weights<<<(prep_total + 255) / 256, 256>>>(ipw, bnw, opw, mnw);

    mamba_actor_kernel<<<2 * B, NT, smem_bytes>>>(
        x, buffer, fiw, fib, cw, cb, dtb, alog,
        Dp, nfw, olw, out);

    finalize_kernel<<<(B * COUT + 255) / 256, 256>>>(fow, fob, olw, olb, out, B);
}

// round 9
// speedup vs baseline: 1.5439x; 1.5439x over previous
#include <cuda_runtime.h>
#include <math.h>

#define EPS      1e-5f
#define LSEQ     32
#define DM       128
#define CIN      96
#define COUT     12
#define DIN      256
#define DST      16
#define NH       8
#define CDIM     288          // DIN + 2*DST
#define EPROJ    552          // 2*DIN + 2*DST + NH
#define TST      40           // hs transposed stride (conflict-free A-frag loads)
#define NT       256
#define MAXB     1024

#define IP_NT    69           // in_proj n-tiles (552/8)
#define IP_KC    16           // in_proj k-chunks (128/8)
#define OP_NT    16           // out_proj n-tiles (128/8)
#define OP_KC    32           // out_proj k-chunks (256/8)

typedef unsigned long long u64;

// device scratch (no allocation): fragment-ordered, tf32 hi/lo split weights
#define IPF_N (4 * IP_NT * IP_KC * 128)   // 565248 floats
#define OPF_N (4 * OP_NT * OP_KC * 128)   // 262144 floats
__device__ float g_ipf[IPF_N];
__device__ float g_opf[OPF_N];
__device__ float g_A[(size_t)MAXB * 2 * DM];

// shared memory layout (floats)
#define OFF_BUF   0                          // 3072
#define OFF_HST   (OFF_BUF + CIN*LSEQ)       // 128*40 = 5120
#define OFF_ZX    (OFF_HST + DM*TST)         // 32*552 = 17664
#define OFF_DT    (OFF_ZX + LSEQ*EPROJ)      // 256
#define OFF_DA    (OFF_DT + LSEQ*NH)         // 256
#define OFF_INV   (OFF_DA + LSEQ*NH)         // 32
#define OFF_INV2  (OFF_INV + LSEQ)           // 32
#define OFF_RED   (OFF_INV2 + LSEQ)          // 256
#define SMEM_FLOATS (OFF_RED + NT)           // 26688 floats = 106752 B

__device__ __forceinline__ float sigmoidf_(float v) {
    return 1.f / (1.f + __expf(-v));
}
__device__ __forceinline__ u64 pk2(float lo, float hi) {
    u64 r; asm("mov.b64 %0,{%1,%2};" : "=l"(r) : "f"(lo), "f"(hi)); return r;
}
__device__ __forceinline__ u64 dup2(float v) { return pk2(v, v); }
__device__ __forceinline__ void upk2(u64 a, float& lo, float& hi) {
    asm("mov.b64 {%0,%1},%2;" : "=f"(lo), "=f"(hi) : "l"(a));
}
__device__ __forceinline__ u64 fma2_(u64 a, u64 b, u64 c) {
    u64 d; asm("fma.rn.f32x2 %0,%1,%2,%3;" : "=l"(d) : "l"(a), "l"(b), "l"(c)); return d;
}
__device__ __forceinline__ u64 mul2_(u64 a, u64 b) {
    u64 d; asm("mul.rn.f32x2 %0,%1,%2;" : "=l"(d) : "l"(a), "l"(b)); return d;
}
__device__ __forceinline__ unsigned f2tf32(float f) {
    unsigned r; asm("cvt.rna.tf32.f32 %0, %1;" : "=r"(r) : "f"(f)); return r;
}
__device__ __forceinline__ void mma_tf32(float* d, const unsigned* a,
                                         unsigned b0, unsigned b1) {
    asm volatile(
        "mma.sync.aligned.m16n8k8.row.col.f32.tf32.tf32.f32 "
        "{%0,%1,%2,%3},{%4,%5,%6,%7},{%8,%9},{%0,%1,%2,%3};"
        : "+f"(d[0]), "+f"(d[1]), "+f"(d[2]), "+f"(d[3])
        : "r"(a[0]), "r"(a[1]), "r"(a[2]), "r"(a[3]), "r"(b0), "r"(b1));
}

// ---- prep: fold norms, split tf32 hi/lo, lay out in B-fragment lane order ---
// in_proj:  W1[k][e] = ipw[e][k]*bnw[k];  B-frag b0=W1[kc*8+(l&3)][n*8+(l>>2)], b1 row+4
// layout g_ipf[blk][n][kc][lane][4] = {b0h, b1h, b0l, b1l}
// out_proj: W2[e][d] = opw[d][e]*mnw[e];  same fragment scheme (K=e, N=d)
__global__ void prep_weights(const float* __restrict__ ipw,
                             const float* __restrict__ bnw,
                             const float* __restrict__ opw,
                             const float* __restrict__ mnw) {
    int i = blockIdx.x * blockDim.x + threadIdx.x;
    if (i < IPF_N) {
        int blk = i / (IP_NT * IP_KC * 128);
        int r   = i - blk * (IP_NT * IP_KC * 128);
        int n   = r / (IP_KC * 128);
        int r2  = r - n * (IP_KC * 128);
        int kc  = r2 >> 7;
        int q   = r2 & 127;
        int lane = q >> 2, comp = q & 3;
        int k = kc * 8 + (lane & 3) + ((comp & 1) ? 4 : 0);
        int e = n * 8 + (lane >> 2);
        float v = ipw[((size_t)blk * EPROJ + e) * DM + k] * bnw[blk * DM + k];
        unsigned hi = f2tf32(v);
        float outv = (comp < 2) ? __uint_as_float(hi)
                   : __uint_as_float(f2tf32(v - __uint_as_float(hi)));
        g_ipf[i] = outv;
    } else if (i < IPF_N + OPF_N) {
        int j   = i - IPF_N;
        int blk = j / (OP_NT * OP_KC * 128);
        int r   = j - blk * (OP_NT * OP_KC * 128);
        int n   = r / (OP_KC * 128);
        int r2  = r - n * (OP_KC * 128);
        int kc  = r2 >> 7;
        int q   = r2 & 127;
        int lane = q >> 2, comp = q & 3;
        int e = kc * 8 + (lane & 3) + ((comp & 1) ? 4 : 0);
        int d = n * 8 + (lane >> 2);
        float v = opw[((size_t)blk * DM + d) * DIN + e] * mnw[blk * DIN + e];
        unsigned hi = f2tf32(v);
        float outv = (comp < 2) ? __uint_as_float(hi)
                   : __uint_as_float(f2tf32(v - __uint_as_float(hi)));
        g_opf[j] = outv;
    }
}

// ---- finalize ----------------------------------------------------------------
__global__ void finalize_kernel(const float* __restrict__ fow,
                                const float* __restrict__ fob,
                                const float* __restrict__ olw,
                                const float* __restrict__ olb,
                                float* __restrict__ out, int B) {
    int idx = blockIdx.x * blockDim.x + threadIdx.x;
    if (idx >= B * COUT) return;
    int b = idx / COUT, o = idx - b * COUT;
    float Swl = 0.f;
#pragma unroll
    for (int t = 0; t < LSEQ; t++) Swl += olw[t];
    const float* A0 = g_A + (size_t)b * 2 * DM;
    float acc = 0.f;
#pragma unroll 4
    for (int d = 0; d < DM; d++) acc = fmaf(fow[o * DM + d], A0[d] + A0[DM + d], acc);
    out[idx] = acc + fob[o] * Swl + olb[0];
}

// ---- main: one CTA per (batch, direction) -------------------------------------
__global__ void __launch_bounds__(NT, 2) mamba_actor_kernel(
    const float* __restrict__ x,        // (B, 96)
    const float* __restrict__ buffer,   // (B, 96, 32)
    const float* __restrict__ fiw,      // (128, 96)
    const float* __restrict__ fib,      // (128,)
    const float* __restrict__ cw,       // (4, 288, 4)
    const float* __restrict__ cb,       // (4, 288)
    const float* __restrict__ dtb,      // (4, 8)
    const float* __restrict__ alog,     // (4, 8)
    const float* __restrict__ Dp,       // (4, 8)
    const float* __restrict__ nfw,      // (2, 128)
    const float* __restrict__ olw,      // (1, 32)
    float* __restrict__ out)
{
    extern __shared__ float sm[];
    float* s_buf  = sm + OFF_BUF;
    float* s_hsT  = sm + OFF_HST;   // [d][t], stride TST
    float* s_zx   = sm + OFF_ZX;    // [t][e], stride EPROJ
    float* s_dt   = sm + OFF_DT;
    float* s_dA   = sm + OFF_DA;
    float* s_inv  = sm + OFF_INV;
    float* s_inv2 = sm + OFF_INV2;
    float* s_red  = sm + OFF_RED;

    const int B    = gridDim.x >> 1;
    const int b    = blockIdx.x >> 1;
    const int dir  = blockIdx.x & 1;
    const int tid  = threadIdx.x;
    const int lane = tid & 31;
    const int warp = tid >> 5;
    const int kb   = lane & 3;      // threadID in group (k row within chunk)
    const int tb   = lane >> 2;     // group id (matrix row / col)

    // ---- Stage 0: shifted buffer -> smem (dir-flipped) + buf output ----------
    {
        const float* bsrc = buffer + (size_t)b * CIN * LSEQ;
        const float* xsrc = x + (size_t)b * CIN;
        float* bdst = out + (size_t)B * COUT + (size_t)b * CIN * LSEQ;
        for (int idx = tid; idx < CIN * LSEQ; idx += NT) {
            int c = idx >> 5, l = idx & 31;
            float v = (l < LSEQ - 1) ? bsrc[c * LSEQ + l + 1] : xsrc[c];
            int ls = dir ? (LSEQ - 1 - l) : l;
            s_buf[c * LSEQ + ls] = v;
            if (dir == 0) bdst[idx] = v;
        }
    }
    __syncthreads();

    // ---- fc_in (f32x2): thread = (d, t-half) ---------------------------------
    {
        int d   = tid >> 1;
        int tph = tid & 1;
        u64 acc2[8];
        u64 bias = dup2(fib[d]);
#pragma unroll
        for (int p = 0; p < 8; p++) acc2[p] = bias;
        const float4* wrow = reinterpret_cast<const float4*>(fiw + d * CIN);
#pragma unroll 2
        for (int cc = 0; cc < CIN / 4; cc++) {
            float4 w4 = wrow[cc];
            u64 w0 = dup2(w4.x), w1 = dup2(w4.y), w2 = dup2(w4.z), w3 = dup2(w4.w);
            const u64* b0 = reinterpret_cast<const u64*>(s_buf + (cc * 4 + 0) * LSEQ + tph * 16);
            const u64* b1 = reinterpret_cast<const u64*>(s_buf + (cc * 4 + 1) * LSEQ + tph * 16);
            const u64* b2 = reinterpret_cast<const u64*>(s_buf + (cc * 4 + 2) * LSEQ + tph * 16);
            const u64* b3 = reinterpret_cast<const u64*>(s_buf + (cc * 4 + 3) * LSEQ + tph * 16);
#pragma unroll
            for (int p = 0; p < 8; p++) {
                acc2[p] = fma2_(b0[p], w0, acc2[p]);
                acc2[p] = fma2_(b1[p], w1, acc2[p]);
                acc2[p] = fma2_(b2[p], w2, acc2[p]);
                acc2[p] = fma2_(b3[p], w3, acc2[p]);
            }
        }
        u64* hdst = reinterpret_cast<u64*>(s_hsT + d * TST + tph * 16);
#pragma unroll
        for (int p = 0; p < 8; p++) hdst[p] = acc2[p];
    }
    __syncthreads();

    for (int l = 0; l < 2; l++) {
        const int blk = dir * 2 + l;

        // ---- block rmsnorm over d (transposed layout) ------------------------
        {
            float s = 0.f;
#pragma unroll
            for (int q = 0; q < 16; q++) {
                float v = s_hsT[(warp * 16 + q) * TST + lane];
                s += v * v;
            }
            s_red[warp * 32 + lane] = s;
        }
        __syncthreads();
        if (tid < 32) {
            float s = 0.f;
#pragma unroll
            for (int w = 0; w < 8; w++) s += s_red[w * 32 + tid];
            s_inv[tid] = rsqrtf(s * (1.f / DM) + EPS);
        }
        __syncthreads();

        // ---- in_proj via tensor cores (3xTF32): D[t][e] = hs . W1 -------------
        {
            const float* Wf = g_ipf + (size_t)blk * (IP_NT * IP_KC * 128);
            float dacc[9][2][4];
#pragma unroll
            for (int j = 0; j < 9; j++)
#pragma unroll
                for (int m = 0; m < 2; m++)
#pragma unroll
                    for (int q = 0; q < 4; q++) dacc[j][m][q] = 0.f;

#pragma unroll 1
            for (int kc = 0; kc < IP_KC; kc++) {
                unsigned ah[2][4], al[2][4];
#pragma unroll
                for (int m = 0; m < 2; m++) {
                    int k0 = kc * 8 + kb;
                    int t0 = m * 16 + tb;
                    float a0 = s_hsT[k0 * TST + t0];
                    float a1 = s_hsT[k0 * TST + t0 + 8];
                    float a2 = s_hsT[(k0 + 4) * TST + t0];
                    float a3 = s_hsT[(k0 + 4) * TST + t0 + 8];
                    ah[m][0] = f2tf32(a0); al[m][0] = f2tf32(a0 - __uint_as_float(ah[m][0]));
                    ah[m][1] = f2tf32(a1); al[m][1] = f2tf32(a1 - __uint_as_float(ah[m][1]));
                    ah[m][2] = f2tf32(a2); al[m][2] = f2tf32(a2 - __uint_as_float(ah[m][2]));
                    ah[m][3] = f2tf32(a3); al[m][3] = f2tf32(a3 - __uint_as_float(ah[m][3]));
                }
#pragma unroll
                for (int j = 0; j < 9; j++) {
                    int n = warp + j * 8;
                    if (n < IP_NT) {
                        float4 bf = *reinterpret_cast<const float4*>(
                            Wf + ((size_t)(n * IP_KC + kc)) * 128 + lane * 4);
                        unsigned b0h = __float_as_uint(bf.x), b1h = __float_as_uint(bf.y);
                        unsigned b0l = __float_as_uint(bf.z), b1l = __float_as_uint(bf.w);
#pragma unroll
                        for (int m = 0; m < 2; m++) {
                            mma_tf32(dacc[j][m], ah[m], b0h, b1h);
                            mma_tf32(dacc[j][m], ah[m], b0l, b1l);
                            mma_tf32(dacc[j][m], al[m], b0h, b1h);
                        }
                    }
                }
            }
            // epilogue: scale rows by inv[t], store to zx
#pragma unroll
            for (int j = 0; j < 9; j++) {
                int n = warp + j * 8;
                if (n < IP_NT) {
#pragma unroll
                    for (int m = 0; m < 2; m++) {
                        int t0 = m * 16 + tb;
                        float i0 = s_inv[t0], i1 = s_inv[t0 + 8];
                        int e0 = n * 8 + 2 * kb;
                        float2 v0 = make_float2(dacc[j][m][0] * i0, dacc[j][m][1] * i0);
                        float2 v1 = make_float2(dacc[j][m][2] * i1, dacc[j][m][3] * i1);
                        *reinterpret_cast<float2*>(s_zx + t0 * EPROJ + e0) = v0;
                        *reinterpret_cast<float2*>(s_zx + (t0 + 8) * EPROJ + e0) = v1;
                    }
                }
            }
        }
        __syncthreads();

        // ---- dt/dA (256 threads == 32 t * 8 heads) + conv boundary pre-reads --
        {
            int t = tid >> 3, h = tid & 7;
            float v  = s_zx[t * EPROJ + DIN + CDIM + h] + dtb[blk * NH + h];
            float sp = (v > 20.f) ? v : log1pf(__expf(v));
            s_dt[t * NH + h] = sp;
            s_dA[t * NH + h] = __expf(-__expf(alog[blk * NH + h]) * sp);
        }
        float pre[2][3];
        {
            int nb = 0;
            for (int u = tid; u < 2 * CDIM; u += NT) {
                if (u >= CDIM) {
                    float* col = s_zx + DIN + (u - CDIM);
                    pre[nb][0] = col[13 * EPROJ];
                    pre[nb][1] = col[14 * EPROJ];
                    pre[nb][2] = col[15 * EPROJ];
                    nb++;
                }
            }
        }
        __syncthreads();

        // ---- causal depthwise conv (k=4) + silu, (c, t-half) units ------------
        {
            int nb = 0;
            for (int u = tid; u < 2 * CDIM; u += NT) {
                int half = (u >= CDIM);
                int c = half ? u - CDIM : u;
                float4 w4 = *reinterpret_cast<const float4*>(cw + ((size_t)blk * CDIM + c) * 4);
                float bb  = cb[blk * CDIM + c];
                float x0, x1, x2;
                if (half) { x0 = pre[nb][0]; x1 = pre[nb][1]; x2 = pre[nb][2]; nb++; }
                else      { x0 = 0.f; x1 = 0.f; x2 = 0.f; }
                float* col = s_zx + DIN + c + (half ? 16 * EPROJ : 0);
#pragma unroll
                for (int tt = 0; tt < 16; tt++) {
                    float xc = col[tt * EPROJ];
                    float o  = fmaf(w4.x, x0, fmaf(w4.y, x1, fmaf(w4.z, x2, fmaf(w4.w, xc, bb))));
                    col[tt * EPROJ] = o * sigmoidf_(o);
                    x0 = x1; x1 = x2; x2 = xc;
                }
            }
        }
        __syncthreads();

        // ---- SSM scan (+ fused gate): thread = (head, p) ----------------------
        {
            int h = tid >> 5;
            u64 st2[NH];
#pragma unroll
            for (int n = 0; n < 8; n++) st2[n] = 0ull;
            float dskip = Dp[blk * NH + h];
            for (int t = 0; t < LSEQ; t++) {
                float* row = s_zx + t * EPROJ;
                float dAv = s_dA[t * NH + h];
                float dtv = s_dt[t * NH + h];
                float xv  = row[DIN + tid];
                u64 dA2  = dup2(dAv);
                u64 dtx2 = dup2(dtv * xv);
                const ulonglong2* Bp = reinterpret_cast<const ulonglong2*>(row + 2 * DIN);
                const ulonglong2* Cp = reinterpret_cast<const ulonglong2*>(row + 2 * DIN + DST);
                u64 y2 = 0ull;
#pragma unroll
                for (int q = 0; q < 4; q++) {
                    ulonglong2 b2 = Bp[q];
                    ulonglong2 c2 = Cp[q];
                    st2[2*q]   = fma2_(st2[2*q],   dA2, mul2_(dtx2, b2.x));
                    y2         = fma2_(st2[2*q],   c2.x, y2);
                    st2[2*q+1] = fma2_(st2[2*q+1], dA2, mul2_(dtx2, b2.y));
                    y2         = fma2_(st2[2*q+1], c2.y, y2);
                }
                float ylo, yhi;
                upk2(y2, ylo, yhi);
                float yv = fmaf(dskip, xv, ylo + yhi);
                float z  = row[tid];
                row[DIN + tid] = yv * z * sigmoidf_(z);   // fused gate
            }
        }
        __syncthreads();

        // ---- mixer rmsnorm factor over gated g --------------------------------
        {
            int t = tid >> 3, part = tid & 7;
            const float4* gp = reinterpret_cast<const float4*>(s_zx + t * EPROJ + DIN + part * 32);
            float s = 0.f;
#pragma unroll
            for (int q = 0; q < 8; q++) {
                float4 v = gp[q];
                s += v.x * v.x + v.y * v.y + v.z * v.z + v.w * v.w;
            }
            s += __shfl_xor_sync(0xffffffffu, s, 1);
            s += __shfl_xor_sync(0xffffffffu, s, 2);
            s += __shfl_xor_sync(0xffffffffu, s, 4);
            if (part == 0) s_inv2[t] = rsqrtf(s * (1.f / DIN) + EPS);
        }
        __syncthreads();

        // ---- out_proj via tensor cores (3xTF32) + residual --------------------
        {
            const float* Wf = g_opf + (size_t)blk * (OP_NT * OP_KC * 128);
            float dacc[2][2][4];
#pragma unroll
            for (int j = 0; j < 2; j++)
#pragma unroll
                for (int m = 0; m < 2; m++)
#pragma unroll
                    for (int q = 0; q < 4; q++) dacc[j][m][q] = 0.f;

#pragma unroll 1
            for (int kc = 0; kc < OP_KC; kc++) {
                unsigned ah[2][4], al[2][4];
#pragma unroll
                for (int m = 0; m < 2; m++) {
                    int e0 = DIN + kc * 8 + kb;
                    int t0 = m * 16 + tb;
                    float a0 = s_zx[t0 * EPROJ + e0];
                    float a1 = s_zx[(t0 + 8) * EPROJ + e0];
                    float a2 = s_zx[t0 * EPROJ + e0 + 4];
                    float a3 = s_zx[(t0 + 8) * EPROJ + e0 + 4];
                    ah[m][0] = f2tf32(a0); al[m][0] = f2tf32(a0 - __uint_as_float(ah[m][0]));
                    ah[m][1] = f2tf32(a1); al[m][1] = f2tf32(a1 - __uint_as_float(ah[m][1]));
                    ah[m][2] = f2tf32(a2); al[m][2] = f2tf32(a2 - __uint_as_float(ah[m][2]));
                    ah[m][3] = f2tf32(a3); al[m][3] = f2tf32(a3 - __uint_as_float(ah[m][3]));
                }
#pragma unroll
                for (int j = 0; j < 2; j++) {
                    int n = warp + j * 8;
                    float4 bf = *reinterpret_cast<const float4*>(
                        Wf + ((size_t)(n * OP_KC + kc)) * 128 + lane * 4);
                    unsigned b0h = __float_as_uint(bf.x), b1h = __float_as_uint(bf.y);
                    unsigned b0l = __float_as_uint(bf.z), b1l = __float_as_uint(bf.w);
#pragma unroll
                    for (int m = 0; m < 2; m++) {
                        mma_tf32(dacc[j][m], ah[m], b0h, b1h);
                        mma_tf32(dacc[j][m], ah[m], b0l, b1l);
                        mma_tf32(dacc[j][m], al[m], b0h, b1h);
                    }
                }
            }
            // epilogue: hsT[d][t] += inv2[t] * D[t][d]
#pragma unroll
            for (int j = 0; j < 2; j++) {
                int n = warp + j * 8;
#pragma unroll
                for (int m = 0; m < 2; m++) {
                    int t0 = m * 16 + tb;
                    float i0 = s_inv2[t0], i1 = s_inv2[t0 + 8];
                    int d0 = n * 8 + 2 * kb;
                    s_hsT[d0 * TST + t0]           += dacc[j][m][0] * i0;
                    s_hsT[(d0 + 1) * TST + t0]     += dacc[j][m][1] * i0;
                    s_hsT[d0 * TST + t0 + 8]       += dacc[j][m][2] * i1;
                    s_hsT[(d0 + 1) * TST + t0 + 8] += dacc[j][m][3] * i1;
                }
            }
        }
        __syncthreads();
    } // layer

    // ---- final rmsnorm(norm_f) over d ------------------------------------------
    {
        float s = 0.f;
#pragma unroll
        for (int q = 0; q < 16; q++) {
            float v = s_hsT[(warp * 16 + q) * TST + lane];
            s += v * v;
        }
        s_red[warp * 32 + lane] = s;
    }
    __syncthreads();
    if (tid < 32) {
        float s = 0.f;
#pragma unroll
        for (int w = 0; w < 8; w++) s += s_red[w * 32 + tid];
        s_inv[tid] = rsqrtf(s * (1.f / DM) + EPS);
    }
    __syncthreads();

    // ---- L-weighted accumulate -> g_A ------------------------------------------
    if (tid < DM) {
        const float* hrow = s_hsT + tid * TST;
        float s = 0.f;
#pragma unroll
        for (int t = 0; t < LSEQ; t++) {
            float wl = olw[dir ? (LSEQ - 1 - t) : t];
            s = fmaf(wl * s_inv[t], hrow[t], s);
        }
        g_A[((size_t)b * 2 + dir) * DM + tid] = s * nfw[dir * DM + tid];
    }
}

extern "C" void kernel_launch(void* const* d_in, const int* in_sizes, int n_in,
                              void* d_out, int out_size) {
    const float* x      = (const float*)d_in[0];
    const float* buffer = (const float*)d_in[1];
    const float* fiw    = (const float*)d_in[2];
    const float* fib    = (const float*)d_in[3];
    const float* bnw    = (const float*)d_in[4];
    const float* ipw    = (const float*)d_in[5];
    const float* cw     = (const float*)d_in[6];
    const float* cb     = (const float*)d_in[7];
    const float* dtb    = (const float*)d_in[8];
    const float* alog   = (const float*)d_in[9];
    const float* Dp     = (const float*)d_in[10];
    const float* mnw    = (const float*)d_in[11];
    const float* opw    = (const float*)d_in[12];
    const float* nfw    = (const float*)d_in[13];
    const float* fow    = (const float*)d_in[14];
    const float* fob    = (const float*)d_in[15];
    const float* olw    = (const float*)d_in[16];
    const float* olb    = (const float*)d_in[17];
    float* out = (float*)d_out;

    int B = in_sizes[0] / CIN;   // 1024
    size_t smem_bytes = (size_t)SMEM_FLOATS * sizeof(float);

    cudaFuncSetAttribute(mamba_actor_kernel,
                         cudaFuncAttributeMaxDynamicSharedMemorySize,
                         (int)smem_bytes);

    int prep_total = IPF_N + OPF_N;
    prep_weights<<<(prep_total + 255) / 256, 256>>>(ipw, bnw, opw, mnw);

    mamba_actor_kernel<<<2 * B, NT, smem_bytes>>>(
        x, buffer, fiw, fib, cw, cb, dtb, alog,
        Dp, nfw, olw, out);

    finalize_kernel<<<(B * COUT + 255) / 256, 256>>>(fow, fob, olw, olb, out, B);
}

// round 10
// speedup vs baseline: 2.2140x; 1.4340x over previous
#include <cuda_runtime.h>
#include <math.h>

#define EPS      1e-5f
#define LSEQ     32
#define DM       128
#define CIN      96
#define COUT     12
#define DIN      256
#define DST      16
#define NH       8
#define CDIM     288          // DIN + 2*DST
#define EPROJ    552          // 2*DIN + 2*DST + NH
#define TST      36           // hs transposed stride (conflict-free k-pair loads)
#define NT       256
#define MAXB     1024

#define IP_NT    69           // in_proj n-tiles (552/8)
#define IP_KC    8            // in_proj k16-chunks (128/16)
#define OP_NT    16           // out_proj n-tiles (128/8)
#define OP_KC    16           // out_proj k16-chunks (256/16)

typedef unsigned long long u64;

// device scratch: bf16 hi/lo fragment-packed weights (one 32-bit word = bf16x2)
#define IPF_N (4 * IP_NT * IP_KC * 128)   // 282624 words
#define OPF_N (4 * OP_NT * OP_KC * 128)   // 131072 words
__device__ unsigned g_ipf[IPF_N];
__device__ unsigned g_opf[OPF_N];
__device__ float g_A[(size_t)MAXB * 2 * DM];

// shared memory layout (floats)
#define OFF_BUF   0                          // 3072
#define OFF_HST   (OFF_BUF + CIN*LSEQ)       // 128*36 = 4608
#define OFF_ZX    (OFF_HST + DM*TST)         // 32*552 = 17664
#define OFF_DT    (OFF_ZX + LSEQ*EPROJ)      // 256
#define OFF_DA    (OFF_DT + LSEQ*NH)         // 256
#define OFF_INV   (OFF_DA + LSEQ*NH)         // 32
#define OFF_INV2  (OFF_INV + LSEQ)           // 32
#define OFF_RED   (OFF_INV2 + LSEQ)          // 256
#define SMEM_FLOATS (OFF_RED + NT)           // 26176 floats = 104704 B

__device__ __forceinline__ float sigmoidf_(float v) {
    return 1.f / (1.f + __expf(-v));
}
__device__ __forceinline__ u64 pk2(float lo, float hi) {
    u64 r; asm("mov.b64 %0,{%1,%2};" : "=l"(r) : "f"(lo), "f"(hi)); return r;
}
__device__ __forceinline__ u64 dup2(float v) { return pk2(v, v); }
__device__ __forceinline__ void upk2(u64 a, float& lo, float& hi) {
    asm("mov.b64 {%0,%1},%2;" : "=f"(lo), "=f"(hi) : "l"(a));
}
__device__ __forceinline__ u64 fma2_(u64 a, u64 b, u64 c) {
    u64 d; asm("fma.rn.f32x2 %0,%1,%2,%3;" : "=l"(d) : "l"(a), "l"(b), "l"(c)); return d;
}
__device__ __forceinline__ u64 mul2_(u64 a, u64 b) {
    u64 d; asm("mul.rn.f32x2 %0,%1,%2;" : "=l"(d) : "l"(a), "l"(b)); return d;
}

// split (v0, v1) -> packed bf16x2 hi (rz-trunc) and lo (rn of residual)
// bf16x2 low half = first element (v0), matching MMA fragment order.
__device__ __forceinline__ void bsplit(float v0, float v1, unsigned& hi, unsigned& lo) {
    unsigned u0 = __float_as_uint(v0), u1 = __float_as_uint(v1);
    asm("prmt.b32 %0,%1,%2,0x7632;" : "=r"(hi) : "r"(u0), "r"(u1));
    float h0 = __uint_as_float(u0 & 0xffff0000u);
    float h1 = __uint_as_float(u1 & 0xffff0000u);
    asm("cvt.rn.bf16x2.f32 %0,%1,%2;" : "=r"(lo) : "f"(v1 - h1), "f"(v0 - h0));
}
__device__ __forceinline__ void mma_bf16(float* d, const unsigned* a,
                                         unsigned b0, unsigned b1) {
    asm volatile(
        "mma.sync.aligned.m16n8k16.row.col.f32.bf16.bf16.f32 "
        "{%0,%1,%2,%3},{%4,%5,%6,%7},{%8,%9},{%0,%1,%2,%3};"
        : "+f"(d[0]), "+f"(d[1]), "+f"(d[2]), "+f"(d[3])
        : "r"(a[0]), "r"(a[1]), "r"(a[2]), "r"(a[3]), "r"(b0), "r"(b1));
}

// ---- prep: fold norms, bf16 hi/lo split, B-fragment lane order --------------
// word layout [blk][n][kc][lane][comp]: comp 0 = b0hi, 1 = b1hi, 2 = b0lo, 3 = b1lo
// b0 covers k = 2c, 2c+1 ; b1 covers k = 2c+8, 2c+9 ; column = n*8 + (lane>>2)
__global__ void prep_weights(const float* __restrict__ ipw,
                             const float* __restrict__ bnw,
                             const float* __restrict__ opw,
                             const float* __restrict__ mnw) {
    int i = blockIdx.x * blockDim.x + threadIdx.x;
    if (i < IPF_N) {
        int blk = i / (IP_NT * IP_KC * 128);
        int r   = i - blk * (IP_NT * IP_KC * 128);
        int n   = r / (IP_KC * 128);
        int q   = r - n * (IP_KC * 128);
        int kc  = q >> 7;
        int rem = q & 127;
        int lane = rem >> 2, comp = rem & 3;
        int g = lane >> 2, c = lane & 3;
        int e  = n * 8 + g;
        int k0 = kc * 16 + 2 * c + ((comp & 1) ? 8 : 0);
        float v0 = ipw[((size_t)blk * EPROJ + e) * DM + k0]     * bnw[blk * DM + k0];
        float v1 = ipw[((size_t)blk * EPROJ + e) * DM + k0 + 1] * bnw[blk * DM + k0 + 1];
        unsigned hi, lo;
        bsplit(v0, v1, hi, lo);
        g_ipf[i] = (comp < 2) ? hi : lo;
    } else if (i < IPF_N + OPF_N) {
        int j   = i - IPF_N;
        int blk = j >> 15;                 // 32768 words per blk
        int r   = j & 32767;
        int n   = r >> 11;                 // 2048 words per n-tile
        int q   = r & 2047;
        int kc  = q >> 7;
        int rem = q & 127;
        int lane = rem >> 2, comp = rem & 3;
        int g = lane >> 2, c = lane & 3;
        int d  = n * 8 + g;
        int e0 = kc * 16 + 2 * c + ((comp & 1) ? 8 : 0);
        float v0 = opw[((size_t)blk * DM + d) * DIN + e0]     * mnw[blk * DIN + e0];
        float v1 = opw[((size_t)blk * DM + d) * DIN + e0 + 1] * mnw[blk * DIN + e0 + 1];
        unsigned hi, lo;
        bsplit(v0, v1, hi, lo);
        g_opf[j] = (comp < 2) ? hi : lo;
    }
}

// ---- finalize ----------------------------------------------------------------
__global__ void finalize_kernel(const float* __restrict__ fow,
                                const float* __restrict__ fob,
                                const float* __restrict__ olw,
                                const float* __restrict__ olb,
                                float* __restrict__ out, int B) {
    int idx = blockIdx.x * blockDim.x + threadIdx.x;
    if (idx >= B * COUT) return;
    int b = idx / COUT, o = idx - b * COUT;
    float Swl = 0.f;
#pragma unroll
    for (int t = 0; t < LSEQ; t++) Swl += olw[t];
    const float* A0 = g_A + (size_t)b * 2 * DM;
    float acc = 0.f;
#pragma unroll 4
    for (int d = 0; d < DM; d++) acc = fmaf(fow[o * DM + d], A0[d] + A0[DM + d], acc);
    out[idx] = acc + fob[o] * Swl + olb[0];
}

// ---- main: one CTA per (batch, direction) -------------------------------------
__global__ void __launch_bounds__(NT, 2) mamba_actor_kernel(
    const float* __restrict__ x,        // (B, 96)
    const float* __restrict__ buffer,   // (B, 96, 32)
    const float* __restrict__ fiw,      // (128, 96)
    const float* __restrict__ fib,      // (128,)
    const float* __restrict__ cw,       // (4, 288, 4)
    const float* __restrict__ cb,       // (4, 288)
    const float* __restrict__ dtb,      // (4, 8)
    const float* __restrict__ alog,     // (4, 8)
    const float* __restrict__ Dp,       // (4, 8)
    const float* __restrict__ nfw,      // (2, 128)
    const float* __restrict__ olw,      // (1, 32)
    float* __restrict__ out)
{
    extern __shared__ float sm[];
    float* s_buf  = sm + OFF_BUF;
    float* s_hsT  = sm + OFF_HST;   // [k][t], stride TST
    float* s_zx   = sm + OFF_ZX;    // [t][e], stride EPROJ
    float* s_dt   = sm + OFF_DT;
    float* s_dA   = sm + OFF_DA;
    float* s_inv  = sm + OFF_INV;
    float* s_inv2 = sm + OFF_INV2;
    float* s_red  = sm + OFF_RED;

    const int B    = gridDim.x >> 1;
    const int b    = blockIdx.x >> 1;
    const int dir  = blockIdx.x & 1;
    const int tid  = threadIdx.x;
    const int lane = tid & 31;
    const int warp = tid >> 5;
    const int kb   = lane & 3;      // c: thread-in-group
    const int tb   = lane >> 2;     // g: group id (row)

    // ---- Stage 0: shifted buffer -> smem (dir-flipped) + buf output ----------
    {
        const float* bsrc = buffer + (size_t)b * CIN * LSEQ;
        const float* xsrc = x + (size_t)b * CIN;
        float* bdst = out + (size_t)B * COUT + (size_t)b * CIN * LSEQ;
        for (int idx = tid; idx < CIN * LSEQ; idx += NT) {
            int c = idx >> 5, l = idx & 31;
            float v = (l < LSEQ - 1) ? bsrc[c * LSEQ + l + 1] : xsrc[c];
            int ls = dir ? (LSEQ - 1 - l) : l;
            s_buf[c * LSEQ + ls] = v;
            if (dir == 0) bdst[idx] = v;
        }
    }
    __syncthreads();

    // ---- fc_in (f32x2): thread = (d, t-half) ---------------------------------
    {
        int d   = tid >> 1;
        int tph = tid & 1;
        u64 acc2[8];
        u64 bias = dup2(fib[d]);
#pragma unroll
        for (int p = 0; p < 8; p++) acc2[p] = bias;
        const float4* wrow = reinterpret_cast<const float4*>(fiw + d * CIN);
#pragma unroll 2
        for (int cc = 0; cc < CIN / 4; cc++) {
            float4 w4 = wrow[cc];
            u64 w0 = dup2(w4.x), w1 = dup2(w4.y), w2 = dup2(w4.z), w3 = dup2(w4.w);
            const u64* b0 = reinterpret_cast<const u64*>(s_buf + (cc * 4 + 0) * LSEQ + tph * 16);
            const u64* b1 = reinterpret_cast<const u64*>(s_buf + (cc * 4 + 1) * LSEQ + tph * 16);
            const u64* b2 = reinterpret_cast<const u64*>(s_buf + (cc * 4 + 2) * LSEQ + tph * 16);
            const u64* b3 = reinterpret_cast<const u64*>(s_buf + (cc * 4 + 3) * LSEQ + tph * 16);
#pragma unroll
            for (int p = 0; p < 8; p++) {
                acc2[p] = fma2_(b0[p], w0, acc2[p]);
                acc2[p] = fma2_(b1[p], w1, acc2[p]);
                acc2[p] = fma2_(b2[p], w2, acc2[p]);
                acc2[p] = fma2_(b3[p], w3, acc2[p]);
            }
        }
        u64* hdst = reinterpret_cast<u64*>(s_hsT + d * TST + tph * 16);
#pragma unroll
        for (int p = 0; p < 8; p++) hdst[p] = acc2[p];
    }
    __syncthreads();

    for (int l = 0; l < 2; l++) {
        const int blk = dir * 2 + l;

        // ---- block rmsnorm over d (transposed layout) ------------------------
        {
            float s = 0.f;
#pragma unroll
            for (int q = 0; q < 16; q++) {
                float v = s_hsT[(warp * 16 + q) * TST + lane];
                s += v * v;
            }
            s_red[warp * 32 + lane] = s;
        }
        __syncthreads();
        if (tid < 32) {
            float s = 0.f;
#pragma unroll
            for (int w = 0; w < 8; w++) s += s_red[w * 32 + tid];
            s_inv[tid] = rsqrtf(s * (1.f / DM) + EPS);
        }
        __syncthreads();

        // ---- in_proj via bf16 tensor cores (3-pass): D[t][e] = hs . W1 --------
        {
            const unsigned* Wf = g_ipf + (size_t)blk * (IP_NT * IP_KC * 128);
            float dacc[9][2][4];
#pragma unroll
            for (int j = 0; j < 9; j++)
#pragma unroll
                for (int m = 0; m < 2; m++)
#pragma unroll
                    for (int q = 0; q < 4; q++) dacc[j][m][q] = 0.f;

#pragma unroll 1
            for (int kc = 0; kc < IP_KC; kc++) {
                unsigned ah[2][4], al[2][4];
#pragma unroll
                for (int m = 0; m < 2; m++) {
#pragma unroll
                    for (int r = 0; r < 4; r++) {
                        int tt = m * 16 + tb + (r & 1) * 8;
                        int k  = kc * 16 + 2 * kb + (r >> 1) * 8;
                        float v0 = s_hsT[k * TST + tt];
                        float v1 = s_hsT[(k + 1) * TST + tt];
                        bsplit(v0, v1, ah[m][r], al[m][r]);
                    }
                }
#pragma unroll
                for (int j = 0; j < 9; j++) {
                    int n = warp + j * 8;
                    if (n < IP_NT) {
                        uint4 bf = *reinterpret_cast<const uint4*>(
                            Wf + ((size_t)(n * IP_KC + kc)) * 128 + lane * 4);
#pragma unroll
                        for (int m = 0; m < 2; m++) {
                            mma_bf16(dacc[j][m], ah[m], bf.x, bf.y);
                            mma_bf16(dacc[j][m], ah[m], bf.z, bf.w);
                            mma_bf16(dacc[j][m], al[m], bf.x, bf.y);
                        }
                    }
                }
            }
            // epilogue: scale rows by inv[t], store to zx
#pragma unroll
            for (int j = 0; j < 9; j++) {
                int n = warp + j * 8;
                if (n < IP_NT) {
#pragma unroll
                    for (int m = 0; m < 2; m++) {
                        int t0 = m * 16 + tb;
                        float i0 = s_inv[t0], i1 = s_inv[t0 + 8];
                        int e0 = n * 8 + 2 * kb;
                        float2 v0 = make_float2(dacc[j][m][0] * i0, dacc[j][m][1] * i0);
                        float2 v1 = make_float2(dacc[j][m][2] * i1, dacc[j][m][3] * i1);
                        *reinterpret_cast<float2*>(s_zx + t0 * EPROJ + e0) = v0;
                        *reinterpret_cast<float2*>(s_zx + (t0 + 8) * EPROJ + e0) = v1;
                    }
                }
            }
        }
        __syncthreads();

        // ---- dt/dA (256 threads == 32 t * 8 heads) + conv boundary pre-reads --
        {
            int t = tid >> 3, h = tid & 7;
            float v  = s_zx[t * EPROJ + DIN + CDIM + h] + dtb[blk * NH + h];
            float sp = (v > 20.f) ? v : log1pf(__expf(v));
            s_dt[t * NH + h] = sp;
            s_dA[t * NH + h] = __expf(-__expf(alog[blk * NH + h]) * sp);
        }
        float pre[2][3];
        {
            int nb = 0;
            for (int u = tid; u < 2 * CDIM; u += NT) {
                if (u >= CDIM) {
                    float* col = s_zx + DIN + (u - CDIM);
                    pre[nb][0] = col[13 * EPROJ];
                    pre[nb][1] = col[14 * EPROJ];
                    pre[nb][2] = col[15 * EPROJ];
                    nb++;
                }
            }
        }
        __syncthreads();

        // ---- causal depthwise conv (k=4) + silu, (c, t-half) units ------------
        {
            int nb = 0;
            for (int u = tid; u < 2 * CDIM; u += NT) {
                int half = (u >= CDIM);
                int c = half ? u - CDIM : u;
                float4 w4 = *reinterpret_cast<const float4*>(cw + ((size_t)blk * CDIM + c) * 4);
                float bb  = cb[blk * CDIM + c];
                float x0, x1, x2;
                if (half) { x0 = pre[nb][0]; x1 = pre[nb][1]; x2 = pre[nb][2]; nb++; }
                else      { x0 = 0.f; x1 = 0.f; x2 = 0.f; }
                float* col = s_zx + DIN + c + (half ? 16 * EPROJ : 0);
#pragma unroll
                for (int tt = 0; tt < 16; tt++) {
                    float xc = col[tt * EPROJ];
                    float o  = fmaf(w4.x, x0, fmaf(w4.y, x1, fmaf(w4.z, x2, fmaf(w4.w, xc, bb))));
                    col[tt * EPROJ] = o * sigmoidf_(o);
                    x0 = x1; x1 = x2; x2 = xc;
                }
            }
        }
        __syncthreads();

        // ---- SSM scan (+ fused gate): thread = (head, p) ----------------------
        {
            int h = tid >> 5;
            u64 st2[NH];
#pragma unroll
            for (int n = 0; n < 8; n++) st2[n] = 0ull;
            float dskip = Dp[blk * NH + h];
            for (int t = 0; t < LSEQ; t++) {
                float* row = s_zx + t * EPROJ;
                float dAv = s_dA[t * NH + h];
                float dtv = s_dt[t * NH + h];
                float xv  = row[DIN + tid];
                u64 dA2  = dup2(dAv);
                u64 dtx2 = dup2(dtv * xv);
                const ulonglong2* Bp = reinterpret_cast<const ulonglong2*>(row + 2 * DIN);
                const ulonglong2* Cp = reinterpret_cast<const ulonglong2*>(row + 2 * DIN + DST);
                u64 y2 = 0ull;
#pragma unroll
                for (int q = 0; q < 4; q++) {
                    ulonglong2 b2 = Bp[q];
                    ulonglong2 c2 = Cp[q];
                    st2[2*q]   = fma2_(st2[2*q],   dA2, mul2_(dtx2, b2.x));
                    y2         = fma2_(st2[2*q],   c2.x, y2);
                    st2[2*q+1] = fma2_(st2[2*q+1], dA2, mul2_(dtx2, b2.y));
                    y2         = fma2_(st2[2*q+1], c2.y, y2);
                }
                float ylo, yhi;
                upk2(y2, ylo, yhi);
                float yv = fmaf(dskip, xv, ylo + yhi);
                float z  = row[tid];
                row[DIN + tid] = yv * z * sigmoidf_(z);   // fused gate
            }
        }
        __syncthreads();

        // ---- mixer rmsnorm factor over gated g --------------------------------
        {
            int t = tid >> 3, part = tid & 7;
            const float4* gp = reinterpret_cast<const float4*>(s_zx + t * EPROJ + DIN + part * 32);
            float s = 0.f;
#pragma unroll
            for (int q = 0; q < 8; q++) {
                float4 v = gp[q];
                s += v.x * v.x + v.y * v.y + v.z * v.z + v.w * v.w;
            }
            s += __shfl_xor_sync(0xffffffffu, s, 1);
            s += __shfl_xor_sync(0xffffffffu, s, 2);
            s += __shfl_xor_sync(0xffffffffu, s, 4);
            if (part == 0) s_inv2[t] = rsqrtf(s * (1.f / DIN) + EPS);
        }
        __syncthreads();

        // ---- out_proj via bf16 tensor cores (3-pass) + residual ---------------
        {
            const unsigned* Wf = g_opf + (size_t)blk * (OP_NT * OP_KC * 128);
            float dacc[2][2][4];
#pragma unroll
            for (int j = 0; j < 2; j++)
#pragma unroll
                for (int m = 0; m < 2; m++)
#pragma unroll
                    for (int q = 0; q < 4; q++) dacc[j][m][q] = 0.f;

#pragma unroll 1
            for (int kc = 0; kc < OP_KC; kc++) {
                unsigned ah[2][4], al[2][4];
#pragma unroll
                for (int m = 0; m < 2; m++) {
#pragma unroll
                    for (int r = 0; r < 4; r++) {
                        int tt = m * 16 + tb + (r & 1) * 8;
                        int e  = DIN + kc * 16 + 2 * kb + (r >> 1) * 8;
                        float2 v = *reinterpret_cast<const float2*>(s_zx + tt * EPROJ + e);
                        bsplit(v.x, v.y, ah[m][r], al[m][r]);
                    }
                }
#pragma unroll
                for (int j = 0; j < 2; j++) {
                    int n = warp + j * 8;
                    uint4 bf = *reinterpret_cast<const uint4*>(
                        Wf + ((size_t)(n * OP_KC + kc)) * 128 + lane * 4);
#pragma unroll
                    for (int m = 0; m < 2; m++) {
                        mma_bf16(dacc[j][m], ah[m], bf.x, bf.y);
                        mma_bf16(dacc[j][m], ah[m], bf.z, bf.w);
                        mma_bf16(dacc[j][m], al[m], bf.x, bf.y);
                    }
                }
            }
            // epilogue: hsT[d][t] += inv2[t] * D[t][d]
#pragma unroll
            for (int j = 0; j < 2; j++) {
                int n = warp + j * 8;
#pragma unroll
                for (int m = 0; m < 2; m++) {
                    int t0 = m * 16 + tb;
                    float i0 = s_inv2[t0], i1 = s_inv2[t0 + 8];
                    int d0 = n * 8 + 2 * kb;
                    s_hsT[d0 * TST + t0]           += dacc[j][m][0] * i0;
                    s_hsT[(d0 + 1) * TST + t0]     += dacc[j][m][1] * i0;
                    s_hsT[d0 * TST + t0 + 8]       += dacc[j][m][2] * i1;
                    s_hsT[(d0 + 1) * TST + t0 + 8] += dacc[j][m][3] * i1;
                }
            }
        }
        __syncthreads();
    } // layer

    // ---- final rmsnorm(norm_f) over d ------------------------------------------
    {
        float s = 0.f;
#pragma unroll
        for (int q = 0; q < 16; q++) {
            float v = s_hsT[(warp * 16 + q) * TST + lane];
            s += v * v;
        }
        s_red[warp * 32 + lane] = s;
    }
    __syncthreads();
    if (tid < 32) {
        float s = 0.f;
#pragma unroll
        for (int w = 0; w < 8; w++) s += s_red[w * 32 + tid];
        s_inv[tid] = rsqrtf(s * (1.f / DM) + EPS);
    }
    __syncthreads();

    // ---- L-weighted accumulate -> g_A ------------------------------------------
    if (tid < DM) {
        const float* hrow = s_hsT + tid * TST;
        float s = 0.f;
#pragma unroll
        for (int t = 0; t < LSEQ; t++) {
            float wl = olw[dir ? (LSEQ - 1 - t) : t];
            s = fmaf(wl * s_inv[t], hrow[t], s);
        }
        g_A[((size_t)b * 2 + dir) * DM + tid] = s * nfw[dir * DM + tid];
    }
}

extern "C" void kernel_launch(void* const* d_in, const int* in_sizes, int n_in,
                              void* d_out, int out_size) {
    const float* x      = (const float*)d_in[0];
    const float* buffer = (const float*)d_in[1];
    const float* fiw    = (const float*)d_in[2];
    const float* fib    = (const float*)d_in[3];
    const float* bnw    = (const float*)d_in[4];
    const float* ipw    = (const float*)d_in[5];
    const float* cw     = (const float*)d_in[6];
    const float* cb     = (const float*)d_in[7];
    const float* dtb    = (const float*)d_in[8];
    const float* alog   = (const float*)d_in[9];
    const float* Dp     = (const float*)d_in[10];
    const float* mnw    = (const float*)d_in[11];
    const float* opw    = (const float*)d_in[12];
    const float* nfw    = (const float*)d_in[13];
    const float* fow    = (const float*)d_in[14];
    const float* fob    = (const float*)d_in[15];
    const float* olw    = (const float*)d_in[16];
    const float* olb    = (const float*)d_in[17];
    float* out = (float*)d_out;

    int B = in_sizes[0] / CIN;   // 1024
    size_t smem_bytes = (size_t)SMEM_FLOATS * sizeof(float);

    cudaFuncSetAttribute(mamba_actor_kernel,
                         cudaFuncAttributeMaxDynamicSharedMemorySize,
                         (int)smem_bytes);

    int prep_total = IPF_N + OPF_N;
    prep_weights<<<(prep_total + 255) / 256, 256>>>(ipw, bnw, opw, mnw);

    mamba_actor_kernel<<<2 * B, NT, smem_bytes>>>(
        x, buffer, fiw, fib, cw, cb, dtb, alog,
        Dp, nfw, olw, out);

    finalize_kernel<<<(B * COUT + 255) / 256, 256>>>(fow, fob, olw, olb, out, B);
}